// round 3
// baseline (speedup 1.0000x reference)
#include <cuda_runtime.h>
#include <math.h>

// Problem constants
constexpr int NB = 32;      // batch
constexpr int NC = 512;     // channels
constexpr int NL = 512;     // length
constexpr int NHEAD = 8;
constexpr int NG = 32;      // groups
constexpr float GEPS = 1e-5f;

// Scratch (static device globals: allocation-free, graph-safe)
__device__ float g_xn[NB * NC * NL];            // 32 MB
__device__ float g_cn[NB * NC * NC];            // 32 MB
__device__ float g_q [NB * NC * NL];            // 32 MB
__device__ float g_kv[NB * NC * 2 * NC];        // 64 MB
__device__ float g_a [NB * NC * NL];            // 32 MB

// ---------------------------------------------------------------------------
// GroupNorm: one block per (batch, group). Each group = 16 channels x 512 =
// 8192 contiguous floats. 256 threads, float4 loads, values held in registers
// across the two passes.
// ---------------------------------------------------------------------------
__global__ __launch_bounds__(256) void groupnorm_kernel(
    const float* __restrict__ in, const float* __restrict__ w,
    const float* __restrict__ bia, float* __restrict__ out)
{
    const int bg = blockIdx.x;
    const int g = bg % NG;
    const float4* src = reinterpret_cast<const float4*>(in) + (size_t)bg * 2048;
    float4* dst = reinterpret_cast<float4*>(out) + (size_t)bg * 2048;
    const int tid = threadIdx.x;

    float s = 0.f, ss = 0.f;
    float4 v[8];
#pragma unroll
    for (int i = 0; i < 8; i++) {
        v[i] = src[tid + i * 256];
        s  += v[i].x + v[i].y + v[i].z + v[i].w;
        ss += v[i].x * v[i].x + v[i].y * v[i].y + v[i].z * v[i].z + v[i].w * v[i].w;
    }
    __shared__ float red[2][8];
#pragma unroll
    for (int o = 16; o > 0; o >>= 1) {
        s  += __shfl_xor_sync(0xffffffffu, s, o);
        ss += __shfl_xor_sync(0xffffffffu, ss, o);
    }
    const int warp = tid >> 5, lane = tid & 31;
    if (lane == 0) { red[0][warp] = s; red[1][warp] = ss; }
    __syncthreads();
    if (warp == 0) {
        s = red[0][lane & 7]; ss = red[1][lane & 7];
#pragma unroll
        for (int o = 4; o > 0; o >>= 1) {
            s  += __shfl_xor_sync(0xffffffffu, s, o);
            ss += __shfl_xor_sync(0xffffffffu, ss, o);
        }
        if (lane == 0) { red[0][0] = s; red[1][0] = ss; }
    }
    __syncthreads();
    s = red[0][0]; ss = red[1][0];
    const float mu  = s * (1.f / 8192.f);
    const float var = ss * (1.f / 8192.f) - mu * mu;
    const float inv = rsqrtf(var + GEPS);
#pragma unroll
    for (int i = 0; i < 8; i++) {
        const int fi = tid + i * 256;          // float4 index in group
        const int c = g * 16 + (fi >> 7);      // (fi*4)/512
        const float sc = w[c] * inv;
        const float sh = bia[c] - mu * sc;
        float4 t = v[i];
        t.x = t.x * sc + sh; t.y = t.y * sc + sh;
        t.z = t.z * sc + sh; t.w = t.w * sc + sh;
        dst[fi] = t;
    }
}

// ---------------------------------------------------------------------------
// Batched fp32 GEMM: C[bz] = A[bz](MxK,row) * B[bz](KxN) (+bias)(+resid)
// BTRANS: B is stored (N,K) row-major (i.e. C = A * B^T of the stored matrix)
// BIAS_ROW: bias indexed by m (row), else by n (col)
// 128x128 tile, BK=16, 256 threads, 8x8 micro-tile.
// All dims are multiples of tile sizes here (no bounds checks).
// ---------------------------------------------------------------------------
template<bool BTRANS, bool BIAS_ROW>
__global__ __launch_bounds__(256) void gemm_kernel(
    const float* __restrict__ A, long long sA,
    const float* __restrict__ B, long long sB,
    float* __restrict__ C, long long sC,
    const float* __restrict__ bias,
    const float* __restrict__ resid, long long sR,
    int M, int N, int K)
{
    __shared__ float As[16][132];
    __shared__ float Bs[16][132];

    const int bz = blockIdx.z;
    const float* Ab = A + sA * bz;
    const float* Bb = B + sB * bz;
    float* Cb = C + sC * bz;
    const int m0 = blockIdx.y * 128, n0 = blockIdx.x * 128;
    const int tid = threadIdx.x;
    const int trow = tid >> 4, tcol = tid & 15;
    const int aRow = tid >> 2, aK = (tid & 3) << 2;

    float acc[8][8];
#pragma unroll
    for (int i = 0; i < 8; i++)
#pragma unroll
        for (int j = 0; j < 8; j++) acc[i][j] = 0.f;

    for (int k0 = 0; k0 < K; k0 += 16) {
        // A tile (transpose into As[k][m])
#pragma unroll
        for (int r = 0; r < 2; r++) {
            const float4 t = *reinterpret_cast<const float4*>(
                Ab + (size_t)(m0 + aRow + r * 64) * K + k0 + aK);
            As[aK + 0][aRow + r * 64] = t.x;
            As[aK + 1][aRow + r * 64] = t.y;
            As[aK + 2][aRow + r * 64] = t.z;
            As[aK + 3][aRow + r * 64] = t.w;
        }
        if (BTRANS) {
#pragma unroll
            for (int r = 0; r < 2; r++) {
                const float4 t = *reinterpret_cast<const float4*>(
                    Bb + (size_t)(n0 + aRow + r * 64) * K + k0 + aK);
                Bs[aK + 0][aRow + r * 64] = t.x;
                Bs[aK + 1][aRow + r * 64] = t.y;
                Bs[aK + 2][aRow + r * 64] = t.z;
                Bs[aK + 3][aRow + r * 64] = t.w;
            }
        } else {
            const int bK = tid >> 5, bN = (tid & 31) << 2;
#pragma unroll
            for (int r = 0; r < 2; r++) {
                const float4 t = *reinterpret_cast<const float4*>(
                    Bb + (size_t)(k0 + bK + r * 8) * N + n0 + bN);
                *reinterpret_cast<float4*>(&Bs[bK + r * 8][bN]) = t;
            }
        }
        __syncthreads();
#pragma unroll
        for (int k = 0; k < 16; k++) {
            float ra[8], rb[8];
#pragma unroll
            for (int i = 0; i < 8; i++) ra[i] = As[k][trow * 8 + i];
#pragma unroll
            for (int j = 0; j < 8; j++) rb[j] = Bs[k][tcol * 8 + j];
#pragma unroll
            for (int i = 0; i < 8; i++)
#pragma unroll
                for (int j = 0; j < 8; j++)
                    acc[i][j] = fmaf(ra[i], rb[j], acc[i][j]);
        }
        __syncthreads();
    }

    const float* Rb = resid ? resid + sR * bz : nullptr;
#pragma unroll
    for (int i = 0; i < 8; i++) {
        const int m = m0 + trow * 8 + i;
        const float bm = BIAS_ROW ? bias[m] : 0.f;
        const size_t off = (size_t)m * N + n0 + tcol * 8;
#pragma unroll
        for (int j = 0; j < 8; j += 4) {
            float4 t;
            t.x = acc[i][j + 0]; t.y = acc[i][j + 1];
            t.z = acc[i][j + 2]; t.w = acc[i][j + 3];
            if (BIAS_ROW) {
                t.x += bm; t.y += bm; t.z += bm; t.w += bm;
            } else {
                const int n = n0 + tcol * 8 + j;
                t.x += bias[n]; t.y += bias[n + 1];
                t.z += bias[n + 2]; t.w += bias[n + 3];
            }
            if (Rb) {
                const float4 r = *reinterpret_cast<const float4*>(Rb + off + j);
                t.x += r.x; t.y += r.y; t.z += r.z; t.w += r.w;
            }
            *reinterpret_cast<float4*>(Cb + off + j) = t;
        }
    }
}

// ---------------------------------------------------------------------------
// Fused attention, fp32 online softmax.
// grid = (L/64 t-tiles, B*NH). block = 256.
// Per (b,h): qh[d,t] = q[b, 64h+d, t]
//            kh[d,s] = kv[b, 32h + d/2,       (d&1)*512 + s]
//            vh[d,s] = kv[b, 256 + 32h + d/2, (d&1)*512 + s]
// logits = (1/8) * qh^T kh ; softmax over s ; O[t,d] = sum_s P[t,s] vh[d,s]
// s processed in 4 chunks of 128.
// ---------------------------------------------------------------------------
constexpr int ATTN_SMEM_FLOATS = 64 * 68 + 64 * 132 + 128 * 68 + 128 * 65 + 192;

__global__ __launch_bounds__(256) void attn_kernel(
    const float* __restrict__ q, const float* __restrict__ kv,
    float* __restrict__ outa)
{
    extern __shared__ float sm[];
    float* Qs = sm;                        // [64][68]  (d, t), pre-scaled by 1/8
    float* Ks = Qs + 64 * 68;              // [64][132] (d, s')
    float* Vs = Ks + 64 * 132;             // [128][68] (s', d)
    float* Ps = Vs + 128 * 68;             // [128][65] (s', t)
    float* rowM = Ps + 128 * 65;           // [64]
    float* rowL = rowM + 64;               // [64]
    float* rowA = rowL + 64;               // [64]

    const int t0 = blockIdx.x * 64;
    const int bh = blockIdx.y;
    const int b = bh >> 3, h = bh & 7;
    const int tid = threadIdx.x;
    const int ty = tid >> 4, tx = tid & 15;
    const int dl = tid >> 2;               // load-row d: 0..63
    const int q4 = tid & 3;

    // Load Q tile, scaled by scale^2 = 1/8
    {
        const float* qb = q + ((size_t)b * NC + h * 64) * NL + t0;
#pragma unroll
        for (int r = 0; r < 4; r++) {
            const int f4 = q4 + r * 4;     // 0..15
            float4 v = *reinterpret_cast<const float4*>(qb + (size_t)dl * NL + f4 * 4);
            v.x *= 0.125f; v.y *= 0.125f; v.z *= 0.125f; v.w *= 0.125f;
            *reinterpret_cast<float4*>(&Qs[dl * 68 + f4 * 4]) = v;
        }
    }
    if (tid < 64) { rowM[tid] = -1e30f; rowL[tid] = 0.f; }

    float O[4][4];
#pragma unroll
    for (int i = 0; i < 4; i++)
#pragma unroll
        for (int j = 0; j < 4; j++) O[i][j] = 0.f;

    const float* kvb = kv + (size_t)b * NC * 1024;
    const int ck = 32 * h + (dl >> 1);
    const int obase = (dl & 1) * 512;

    for (int sc = 0; sc < 4; sc++) {
        // ---- load K and V chunk (coalesced float4 along s') ----
        const float* krow = kvb + (size_t)ck * 1024 + obase + sc * 128;
        const float* vrow = kvb + (size_t)(256 + ck) * 1024 + obase + sc * 128;
#pragma unroll
        for (int r = 0; r < 8; r++) {
            const int s4 = q4 + r * 4;     // 0..31
            const float4 t = *reinterpret_cast<const float4*>(krow + s4 * 4);
            *reinterpret_cast<float4*>(&Ks[dl * 132 + s4 * 4]) = t;
            const float4 u = *reinterpret_cast<const float4*>(vrow + s4 * 4);
            Vs[(s4 * 4 + 0) * 68 + dl] = u.x;
            Vs[(s4 * 4 + 1) * 68 + dl] = u.y;
            Vs[(s4 * 4 + 2) * 68 + dl] = u.z;
            Vs[(s4 * 4 + 3) * 68 + dl] = u.w;
        }
        __syncthreads();

        // ---- Phase A: S = Q^T K (thread owns 4t x 8s), softmax update ----
        float S[4][8];
#pragma unroll
        for (int i = 0; i < 4; i++)
#pragma unroll
            for (int j = 0; j < 8; j++) S[i][j] = 0.f;

#pragma unroll 8
        for (int d = 0; d < 64; d++) {
            float qv[4];
#pragma unroll
            for (int i = 0; i < 4; i++) qv[i] = Qs[d * 68 + ty * 4 + i];
            float kvv[8];
            *reinterpret_cast<float4*>(&kvv[0]) =
                *reinterpret_cast<const float4*>(&Ks[d * 132 + tx * 8]);
            *reinterpret_cast<float4*>(&kvv[4]) =
                *reinterpret_cast<const float4*>(&Ks[d * 132 + tx * 8 + 4]);
#pragma unroll
            for (int i = 0; i < 4; i++)
#pragma unroll
                for (int j = 0; j < 8; j++)
                    S[i][j] = fmaf(qv[i], kvv[j], S[i][j]);
        }

        float mx[4];
#pragma unroll
        for (int i = 0; i < 4; i++) {
            float m = S[i][0];
#pragma unroll
            for (int j = 1; j < 8; j++) m = fmaxf(m, S[i][j]);
            mx[i] = m;
        }
#pragma unroll
        for (int o = 8; o > 0; o >>= 1)
#pragma unroll
            for (int i = 0; i < 4; i++)
                mx[i] = fmaxf(mx[i], __shfl_xor_sync(0xffffffffu, mx[i], o));

        float al[4], mn[4], rs[4];
#pragma unroll
        for (int i = 0; i < 4; i++) {
            const float mo = rowM[ty * 4 + i];
            mn[i] = fmaxf(mo, mx[i]);
            al[i] = __expf(mo - mn[i]);
            rs[i] = 0.f;
        }
#pragma unroll
        for (int i = 0; i < 4; i++)
#pragma unroll
            for (int j = 0; j < 8; j++) {
                const float p = __expf(S[i][j] - mn[i]);
                rs[i] += p;
                Ps[(tx * 8 + j) * 65 + ty * 4 + i] = p;
            }
#pragma unroll
        for (int o = 8; o > 0; o >>= 1)
#pragma unroll
            for (int i = 0; i < 4; i++)
                rs[i] += __shfl_xor_sync(0xffffffffu, rs[i], o);
        if (tx == 0) {
#pragma unroll
            for (int i = 0; i < 4; i++) {
                const int t = ty * 4 + i;
                rowM[t] = mn[i];
                rowL[t] = rowL[t] * al[i] + rs[i];
                rowA[t] = al[i];
            }
        }
        __syncthreads();

        // ---- Phase B: O update (thread owns 4t x 4d) ----
        float alv[4];
#pragma unroll
        for (int i = 0; i < 4; i++) alv[i] = rowA[ty * 4 + i];
#pragma unroll
        for (int i = 0; i < 4; i++)
#pragma unroll
            for (int j = 0; j < 4; j++) O[i][j] *= alv[i];

#pragma unroll 8
        for (int s = 0; s < 128; s++) {
            float pv[4];
#pragma unroll
            for (int i = 0; i < 4; i++) pv[i] = Ps[s * 65 + ty * 4 + i];
            const float4 vv = *reinterpret_cast<const float4*>(&Vs[s * 68 + tx * 4]);
#pragma unroll
            for (int i = 0; i < 4; i++) {
                O[i][0] = fmaf(pv[i], vv.x, O[i][0]);
                O[i][1] = fmaf(pv[i], vv.y, O[i][1]);
                O[i][2] = fmaf(pv[i], vv.z, O[i][2]);
                O[i][3] = fmaf(pv[i], vv.w, O[i][3]);
            }
        }
        __syncthreads();
    }

    // Finalize: stage O/l through Qs as [d][t], then coalesced writeback
    float inv[4];
#pragma unroll
    for (int i = 0; i < 4; i++) inv[i] = 1.f / rowL[ty * 4 + i];
#pragma unroll
    for (int i = 0; i < 4; i++)
#pragma unroll
        for (int j = 0; j < 4; j++)
            Qs[(tx * 4 + j) * 68 + ty * 4 + i] = O[i][j] * inv[i];
    __syncthreads();
    {
        float* ab = outa + ((size_t)b * NC + h * 64) * NL + t0;
#pragma unroll
        for (int r = 0; r < 4; r++) {
            const int f4 = q4 + r * 4;
            float4 v;
            v.x = Qs[dl * 68 + f4 * 4 + 0];
            v.y = Qs[dl * 68 + f4 * 4 + 1];
            v.z = Qs[dl * 68 + f4 * 4 + 2];
            v.w = Qs[dl * 68 + f4 * 4 + 3];
            *reinterpret_cast<float4*>(ab + (size_t)dl * NL + f4 * 4) = v;
        }
    }
}

// ---------------------------------------------------------------------------
extern "C" void kernel_launch(void* const* d_in, const int* in_sizes, int n_in,
                              void* d_out, int out_size)
{
    const float* x      = (const float*)d_in[0];
    const float* ctx    = (const float*)d_in[1];
    const float* norm_w = (const float*)d_in[2];
    const float* norm_b = (const float*)d_in[3];
    const float* q_w    = (const float*)d_in[4];
    const float* q_b    = (const float*)d_in[5];
    const float* kv_w   = (const float*)d_in[6];
    const float* kv_b   = (const float*)d_in[7];
    const float* proj_w = (const float*)d_in[8];
    const float* proj_b = (const float*)d_in[9];
    float* out = (float*)d_out;

    float *xn, *cn, *qp, *kvp, *ap;
    cudaGetSymbolAddress((void**)&xn,  g_xn);
    cudaGetSymbolAddress((void**)&cn,  g_cn);
    cudaGetSymbolAddress((void**)&qp,  g_q);
    cudaGetSymbolAddress((void**)&kvp, g_kv);
    cudaGetSymbolAddress((void**)&ap,  g_a);

    constexpr int ATTN_SMEM = ATTN_SMEM_FLOATS * 4;  // ~117 KB
    cudaFuncSetAttribute(attn_kernel,
                         cudaFuncAttributeMaxDynamicSharedMemorySize, ATTN_SMEM);

    // GroupNorm of x and context
    groupnorm_kernel<<<NB * NG, 256>>>(x,   norm_w, norm_b, xn);
    groupnorm_kernel<<<NB * NG, 256>>>(ctx, norm_w, norm_b, cn);

    // q[b,o,l] = q_w(o,c) * xn[b,c,l] + q_b[o]
    gemm_kernel<false, true><<<dim3(4, 4, NB), 256>>>(
        q_w, 0, xn, (long long)NC * NL, qp, (long long)NC * NL,
        q_b, nullptr, 0, NC, NL, NC);

    // kv[b,c,o] = cn[b,c,l] * kv_w(o,l) + kv_b[o]   (B transposed, bias per col)
    gemm_kernel<true, false><<<dim3(8, 4, NB), 256>>>(
        cn, (long long)NC * NC, kv_w, 0, kvp, (long long)NC * 2 * NC,
        kv_b, nullptr, 0, NC, 2 * NC, NC);

    // attention -> a[b,c,l]
    attn_kernel<<<dim3(8, NB * NHEAD), 256, ATTN_SMEM>>>(qp, kvp, ap);

    // out = x + proj_w(o,c) * a[b,c,l] + proj_b[o]
    gemm_kernel<false, true><<<dim3(4, 4, NB), 256>>>(
        proj_w, 0, ap, (long long)NC * NL, out, (long long)NC * NL,
        proj_b, x, (long long)NC * NL, NC, NL, NC);
}

// round 5
// speedup vs baseline: 1.7075x; 1.7075x over previous
#include <cuda_runtime.h>
#include <math.h>
#include <stdint.h>

constexpr int NB = 32;      // batch
constexpr int NC = 512;     // channels
constexpr int NL = 512;     // length
constexpr int NG = 32;      // groups
constexpr float GEPS = 1e-5f;

// Scratch (static device globals: allocation-free, graph-safe)
__device__ float g_xnT[NB * NL * NC];           // x groupnorm, TRANSPOSED [l][c]
__device__ float g_cn [NB * NC * NC];           // ctx groupnorm, natural [c][l]
__device__ float g_q  [NB * NC * NL];           // q, [o][l]
__device__ float g_kv [NB * NC * 2 * NC];       // kv, [c][o]
__device__ float g_aT [NB * NL * NC];           // attn out, TRANSPOSED [l][c]

// ===========================================================================
// PTX helpers (plain sm_100-compatible: cp.async + mma.sync tf32)
// ===========================================================================
__device__ __forceinline__ uint32_t smem_u32(const void* p) {
    uint32_t a;
    asm("{ .reg .u64 t; cvta.to.shared.u64 t, %1; cvt.u32.u64 %0, t; }"
        : "=r"(a) : "l"(p));
    return a;
}
__device__ __forceinline__ void cp_async16(uint32_t dst, const float* src) {
    asm volatile("{ .reg .u64 g; cvta.to.global.u64 g, %1; "
                 "cp.async.cg.shared.global [%0], [g], 16; }"
                 :: "r"(dst), "l"(src) : "memory");
}
__device__ __forceinline__ uint32_t f2tf32(float f) {
    uint32_t u;
    asm("cvt.rna.tf32.f32 %0, %1;" : "=r"(u) : "f"(f));
    return u;
}
__device__ __forceinline__ void mma_tf32_16x8x8(
    float& c0, float& c1, float& c2, float& c3,
    uint32_t a0, uint32_t a1, uint32_t a2, uint32_t a3,
    uint32_t b0, uint32_t b1)
{
    asm volatile(
        "mma.sync.aligned.m16n8k8.row.col.f32.tf32.tf32.f32 "
        "{%0,%1,%2,%3}, {%4,%5,%6,%7}, {%8,%9}, {%0,%1,%2,%3};"
        : "+f"(c0), "+f"(c1), "+f"(c2), "+f"(c3)
        : "r"(a0), "r"(a1), "r"(a2), "r"(a3), "r"(b0), "r"(b1));
}

// ===========================================================================
// GroupNorm: one block per (batch, group). TRANS=true writes out[l][c] layout.
// ===========================================================================
template<bool TRANS>
__global__ __launch_bounds__(256) void groupnorm_kernel(
    const float* __restrict__ in, const float* __restrict__ w,
    const float* __restrict__ bia, float* __restrict__ out)
{
    const int bg = blockIdx.x;
    const int g = bg % NG;
    const float4* src = reinterpret_cast<const float4*>(in) + (size_t)bg * 2048;
    const int tid = threadIdx.x;

    float s = 0.f, ss = 0.f;
    float4 v[8];
#pragma unroll
    for (int i = 0; i < 8; i++) {
        v[i] = src[tid + i * 256];
        s  += v[i].x + v[i].y + v[i].z + v[i].w;
        ss += v[i].x * v[i].x + v[i].y * v[i].y + v[i].z * v[i].z + v[i].w * v[i].w;
    }
    __shared__ float red[2][8];
#pragma unroll
    for (int o = 16; o > 0; o >>= 1) {
        s  += __shfl_xor_sync(0xffffffffu, s, o);
        ss += __shfl_xor_sync(0xffffffffu, ss, o);
    }
    const int warp = tid >> 5, lane = tid & 31;
    if (lane == 0) { red[0][warp] = s; red[1][warp] = ss; }
    __syncthreads();
    if (warp == 0) {
        s = red[0][lane & 7]; ss = red[1][lane & 7];
#pragma unroll
        for (int o = 4; o > 0; o >>= 1) {
            s  += __shfl_xor_sync(0xffffffffu, s, o);
            ss += __shfl_xor_sync(0xffffffffu, ss, o);
        }
        if (lane == 0) { red[0][0] = s; red[1][0] = ss; }
    }
    __syncthreads();
    s = red[0][0]; ss = red[1][0];
    const float mu  = s * (1.f / 8192.f);
    const float var = ss * (1.f / 8192.f) - mu * mu;
    const float inv = rsqrtf(var + GEPS);

    if constexpr (!TRANS) {
        float4* dst = reinterpret_cast<float4*>(out) + (size_t)bg * 2048;
#pragma unroll
        for (int i = 0; i < 8; i++) {
            const int fi = tid + i * 256;
            const int c = g * 16 + (fi >> 7);
            const float sc = w[c] * inv;
            const float sh = bia[c] - mu * sc;
            float4 t = v[i];
            t.x = t.x * sc + sh; t.y = t.y * sc + sh;
            t.z = t.z * sc + sh; t.w = t.w * sc + sh;
            dst[fi] = t;
        }
    } else {
        __shared__ float st[16 * 516];
#pragma unroll
        for (int i = 0; i < 8; i++) {
            const int fi = tid + i * 256;
            const int cl = fi >> 7;               // local channel 0..15
            const int c = g * 16 + cl;
            const float sc = w[c] * inv;
            const float sh = bia[c] - mu * sc;
            float4 t = v[i];
            t.x = t.x * sc + sh; t.y = t.y * sc + sh;
            t.z = t.z * sc + sh; t.w = t.w * sc + sh;
            *reinterpret_cast<float4*>(&st[cl * 516 + (fi & 127) * 4]) = t;
        }
        __syncthreads();
        float* ob = out + (size_t)(bg >> 5) * NL * NC + g * 16;
        const int c4 = tid & 3;
#pragma unroll
        for (int r = 0; r < 8; r++) {
            const int l = (tid >> 2) + r * 64;
            float4 t;
            t.x = st[(c4 * 4 + 0) * 516 + l];
            t.y = st[(c4 * 4 + 1) * 516 + l];
            t.z = st[(c4 * 4 + 2) * 516 + l];
            t.w = st[(c4 * 4 + 3) * 516 + l];
            *reinterpret_cast<float4*>(ob + (size_t)l * NC + c4 * 4) = t;
        }
    }
}

// ===========================================================================
// tf32 mma.sync GEMM:  C[bz] tile(128x128) = A[M,K](K-major) * B[N,K](K-major)^T
// 8 warps (2x4), warp tile 64x32, m16n8k8, BK=32, cp.async double buffer.
// smem row stride 36 floats -> conflict-free fragment LDS.
// ===========================================================================
constexpr int GEMM_SMEM_BYTES = 4 * 128 * 36 * 4;   // 73728

template<bool BIAS_ROW, bool HAS_RES>
__global__ __launch_bounds__(256, 2) void gemm_mma(
    const float* __restrict__ A, long long sA,
    const float* __restrict__ B, long long sB,
    float* __restrict__ C, long long sC,
    const float* __restrict__ bias,
    const float* __restrict__ resid, long long sR,
    int N, int K)
{
    extern __shared__ float sm[];
    // float offsets: A0=0, A1=4608, B0=9216, B1=13824 (each tile 128*36)
    const uint32_t sb = smem_u32(sm);

    const int tid = threadIdx.x;
    const int lane = tid & 31, wid = tid >> 5;
    const int wm = wid >> 2, wn = wid & 3;           // 2 x 4 warp grid
    const int bz = blockIdx.z;
    const int m0 = blockIdx.y * 128, n0 = blockIdx.x * 128;
    const float* Ab = A + (size_t)sA * bz + (size_t)m0 * K;
    const float* Bb = B + (size_t)sB * bz + (size_t)n0 * K;

    const int ldrow = tid >> 3;        // 0..31 (x4 phases -> 128 rows? no: idx>>3)
    (void)ldrow;

    auto loadTile = [&](uint32_t sbase, const float* g) {
#pragma unroll
        for (int i = 0; i < 4; i++) {
            const int idx = tid + i * 256;           // 0..1023
            const int row = idx >> 3, c16 = idx & 7;
            cp_async16(sbase + row * 144 + c16 * 16,
                       g + (size_t)row * K + c16 * 4);
        }
    };

    float acc[4][4][4];
#pragma unroll
    for (int a = 0; a < 4; a++)
#pragma unroll
        for (int b = 0; b < 4; b++)
#pragma unroll
            for (int c = 0; c < 4; c++) acc[a][b][c] = 0.f;

    const int NT = K >> 5;             // K chunks of 32

    // prologue
    loadTile(sb, Ab);
    loadTile(sb + 9216 * 4, Bb);
    asm volatile("cp.async.commit_group;" ::: "memory");

    const int r = lane >> 2, cq = lane & 3;

    for (int kt = 0; kt < NT; kt++) {
        asm volatile("cp.async.wait_group 0;" ::: "memory");
        __syncthreads();
        if (kt + 1 < NT) {
            const int s = (kt + 1) & 1;
            loadTile(sb + s * 4608 * 4, Ab + (kt + 1) * 32);
            loadTile(sb + (9216 + s * 4608) * 4, Bb + (kt + 1) * 32);
            asm volatile("cp.async.commit_group;" ::: "memory");
        }
        const int s = kt & 1;
        const float* a_ = sm + s * 4608 + (wm * 64 + r) * 36 + cq;
        const float* b_ = sm + 9216 + s * 4608 + (wn * 32 + r) * 36 + cq;
#pragma unroll
        for (int k8 = 0; k8 < 4; k8++) {
            uint32_t aF[4][4];
#pragma unroll
            for (int mt = 0; mt < 4; mt++) {
                const float* p = a_ + mt * 576 + k8 * 8;
                aF[mt][0] = f2tf32(p[0]);
                aF[mt][1] = f2tf32(p[288]);
                aF[mt][2] = f2tf32(p[4]);
                aF[mt][3] = f2tf32(p[292]);
            }
            uint32_t bF[4][2];
#pragma unroll
            for (int nt = 0; nt < 4; nt++) {
                const float* p = b_ + nt * 288 + k8 * 8;
                bF[nt][0] = f2tf32(p[0]);
                bF[nt][1] = f2tf32(p[4]);
            }
#pragma unroll
            for (int mt = 0; mt < 4; mt++)
#pragma unroll
                for (int nt = 0; nt < 4; nt++)
                    mma_tf32_16x8x8(acc[mt][nt][0], acc[mt][nt][1],
                                    acc[mt][nt][2], acc[mt][nt][3],
                                    aF[mt][0], aF[mt][1], aF[mt][2], aF[mt][3],
                                    bF[nt][0], bF[nt][1]);
        }
    }

    // epilogue
    float* Cb = C + (size_t)sC * bz;
    const float* Rb = HAS_RES ? (resid + (size_t)sR * bz) : nullptr;
    const int m0w = m0 + wm * 64, n0w = n0 + wn * 32;
#pragma unroll
    for (int mt = 0; mt < 4; mt++) {
        const int r0 = m0w + mt * 16 + (lane >> 2);
        const float bm0 = BIAS_ROW ? __ldg(bias + r0) : 0.f;
        const float bm1 = BIAS_ROW ? __ldg(bias + r0 + 8) : 0.f;
#pragma unroll
        for (int nt = 0; nt < 4; nt++) {
            const int c0 = n0w + nt * 8 + (lane & 3) * 2;
            float bc0 = 0.f, bc1 = 0.f;
            if (!BIAS_ROW) { bc0 = __ldg(bias + c0); bc1 = __ldg(bias + c0 + 1); }
            float2 v0, v1;
            v0.x = acc[mt][nt][0] + (BIAS_ROW ? bm0 : bc0);
            v0.y = acc[mt][nt][1] + (BIAS_ROW ? bm0 : bc1);
            v1.x = acc[mt][nt][2] + (BIAS_ROW ? bm1 : bc0);
            v1.y = acc[mt][nt][3] + (BIAS_ROW ? bm1 : bc1);
            const size_t o0 = (size_t)r0 * N + c0;
            const size_t o1 = (size_t)(r0 + 8) * N + c0;
            if (HAS_RES) {
                const float2 q0 = *reinterpret_cast<const float2*>(Rb + o0);
                const float2 q1 = *reinterpret_cast<const float2*>(Rb + o1);
                v0.x += q0.x; v0.y += q0.y;
                v1.x += q1.x; v1.y += q1.y;
            }
            *reinterpret_cast<float2*>(Cb + o0) = v0;
            *reinterpret_cast<float2*>(Cb + o1) = v1;
        }
    }
}

// ===========================================================================
// Fused attention, fp32 online softmax (output TRANSPOSED [l][c]).
// grid = (L/64 t-tiles, B*NH). block = 256.
// ===========================================================================
constexpr int ATTN_SMEM_FLOATS = 64 * 68 + 64 * 132 + 128 * 68 + 128 * 65 + 192;

__global__ __launch_bounds__(256) void attn_kernel(
    const float* __restrict__ q, const float* __restrict__ kv,
    float* __restrict__ outaT)
{
    extern __shared__ float smf[];
    float* Qs = smf;                       // [64][68]
    float* Ks = Qs + 64 * 68;              // [64][132]
    float* Vs = Ks + 64 * 132;             // [128][68]
    float* Ps = Vs + 128 * 68;             // [128][65]
    float* rowM = Ps + 128 * 65;
    float* rowL = rowM + 64;
    float* rowA = rowL + 64;

    const int t0 = blockIdx.x * 64;
    const int bh = blockIdx.y;
    const int b = bh >> 3, h = bh & 7;
    const int tid = threadIdx.x;
    const int ty = tid >> 4, tx = tid & 15;
    const int dl = tid >> 2;
    const int q4 = tid & 3;

    {
        const float* qb = q + ((size_t)b * NC + h * 64) * NL + t0;
#pragma unroll
        for (int r = 0; r < 4; r++) {
            const int f4 = q4 + r * 4;
            float4 v = *reinterpret_cast<const float4*>(qb + (size_t)dl * NL + f4 * 4);
            v.x *= 0.125f; v.y *= 0.125f; v.z *= 0.125f; v.w *= 0.125f;
            *reinterpret_cast<float4*>(&Qs[dl * 68 + f4 * 4]) = v;
        }
    }
    if (tid < 64) { rowM[tid] = -1e30f; rowL[tid] = 0.f; }

    float O[4][4];
#pragma unroll
    for (int i = 0; i < 4; i++)
#pragma unroll
        for (int j = 0; j < 4; j++) O[i][j] = 0.f;

    const float* kvb = kv + (size_t)b * NC * 1024;
    const int ck = 32 * h + (dl >> 1);
    const int obase = (dl & 1) * 512;

    for (int sc = 0; sc < 4; sc++) {
        const float* krow = kvb + (size_t)ck * 1024 + obase + sc * 128;
        const float* vrow = kvb + (size_t)(256 + ck) * 1024 + obase + sc * 128;
#pragma unroll
        for (int r = 0; r < 8; r++) {
            const int s4 = q4 + r * 4;
            const float4 t = *reinterpret_cast<const float4*>(krow + s4 * 4);
            *reinterpret_cast<float4*>(&Ks[dl * 132 + s4 * 4]) = t;
            const float4 u = *reinterpret_cast<const float4*>(vrow + s4 * 4);
            Vs[(s4 * 4 + 0) * 68 + dl] = u.x;
            Vs[(s4 * 4 + 1) * 68 + dl] = u.y;
            Vs[(s4 * 4 + 2) * 68 + dl] = u.z;
            Vs[(s4 * 4 + 3) * 68 + dl] = u.w;
        }
        __syncthreads();

        float S[4][8];
#pragma unroll
        for (int i = 0; i < 4; i++)
#pragma unroll
            for (int j = 0; j < 8; j++) S[i][j] = 0.f;

#pragma unroll 8
        for (int d = 0; d < 64; d++) {
            float qv[4];
#pragma unroll
            for (int i = 0; i < 4; i++) qv[i] = Qs[d * 68 + ty * 4 + i];
            float kvv[8];
            *reinterpret_cast<float4*>(&kvv[0]) =
                *reinterpret_cast<const float4*>(&Ks[d * 132 + tx * 8]);
            *reinterpret_cast<float4*>(&kvv[4]) =
                *reinterpret_cast<const float4*>(&Ks[d * 132 + tx * 8 + 4]);
#pragma unroll
            for (int i = 0; i < 4; i++)
#pragma unroll
                for (int j = 0; j < 8; j++)
                    S[i][j] = fmaf(qv[i], kvv[j], S[i][j]);
        }

        float mx[4];
#pragma unroll
        for (int i = 0; i < 4; i++) {
            float m = S[i][0];
#pragma unroll
            for (int j = 1; j < 8; j++) m = fmaxf(m, S[i][j]);
            mx[i] = m;
        }
#pragma unroll
        for (int o = 8; o > 0; o >>= 1)
#pragma unroll
            for (int i = 0; i < 4; i++)
                mx[i] = fmaxf(mx[i], __shfl_xor_sync(0xffffffffu, mx[i], o));

        float al[4], mn[4], rs[4];
#pragma unroll
        for (int i = 0; i < 4; i++) {
            const float mo = rowM[ty * 4 + i];
            mn[i] = fmaxf(mo, mx[i]);
            al[i] = __expf(mo - mn[i]);
            rs[i] = 0.f;
        }
#pragma unroll
        for (int i = 0; i < 4; i++)
#pragma unroll
            for (int j = 0; j < 8; j++) {
                const float p = __expf(S[i][j] - mn[i]);
                rs[i] += p;
                Ps[(tx * 8 + j) * 65 + ty * 4 + i] = p;
            }
#pragma unroll
        for (int o = 8; o > 0; o >>= 1)
#pragma unroll
            for (int i = 0; i < 4; i++)
                rs[i] += __shfl_xor_sync(0xffffffffu, rs[i], o);
        if (tx == 0) {
#pragma unroll
            for (int i = 0; i < 4; i++) {
                const int t = ty * 4 + i;
                rowM[t] = mn[i];
                rowL[t] = rowL[t] * al[i] + rs[i];
                rowA[t] = al[i];
            }
        }
        __syncthreads();

        float alv[4];
#pragma unroll
        for (int i = 0; i < 4; i++) alv[i] = rowA[ty * 4 + i];
#pragma unroll
        for (int i = 0; i < 4; i++)
#pragma unroll
            for (int j = 0; j < 4; j++) O[i][j] *= alv[i];

#pragma unroll 8
        for (int s = 0; s < 128; s++) {
            float pv[4];
#pragma unroll
            for (int i = 0; i < 4; i++) pv[i] = Ps[s * 65 + ty * 4 + i];
            const float4 vv = *reinterpret_cast<const float4*>(&Vs[s * 68 + tx * 4]);
#pragma unroll
            for (int i = 0; i < 4; i++) {
                O[i][0] = fmaf(pv[i], vv.x, O[i][0]);
                O[i][1] = fmaf(pv[i], vv.y, O[i][1]);
                O[i][2] = fmaf(pv[i], vv.z, O[i][2]);
                O[i][3] = fmaf(pv[i], vv.w, O[i][3]);
            }
        }
        __syncthreads();
    }

    // Finalize: stage O as [t][d] in Qs, then coalesced TRANSPOSED writeback
    float inv[4];
#pragma unroll
    for (int i = 0; i < 4; i++) inv[i] = 1.f / rowL[ty * 4 + i];
#pragma unroll
    for (int i = 0; i < 4; i++)
#pragma unroll
        for (int j = 0; j < 4; j++)
            Qs[(ty * 4 + i) * 68 + tx * 4 + j] = O[i][j] * inv[i];
    __syncthreads();
    {
        // aT[b][l][c] : c = h*64 + d
        float* ab = outaT + ((size_t)b * NL + t0) * NC + h * 64;
        const int d4 = tid & 15;
#pragma unroll
        for (int r = 0; r < 4; r++) {
            const int t = (tid >> 4) + r * 16;
            const float4 v = *reinterpret_cast<const float4*>(&Qs[t * 68 + d4 * 4]);
            *reinterpret_cast<float4*>(ab + (size_t)t * NC + d4 * 4) = v;
        }
    }
}

// ===========================================================================
extern "C" void kernel_launch(void* const* d_in, const int* in_sizes, int n_in,
                              void* d_out, int out_size)
{
    const float* x      = (const float*)d_in[0];
    const float* ctx    = (const float*)d_in[1];
    const float* norm_w = (const float*)d_in[2];
    const float* norm_b = (const float*)d_in[3];
    const float* q_w    = (const float*)d_in[4];
    const float* q_b    = (const float*)d_in[5];
    const float* kv_w   = (const float*)d_in[6];
    const float* kv_b   = (const float*)d_in[7];
    const float* proj_w = (const float*)d_in[8];
    const float* proj_b = (const float*)d_in[9];
    float* out = (float*)d_out;

    float *xnT, *cn, *qp, *kvp, *aT;
    cudaGetSymbolAddress((void**)&xnT, g_xnT);
    cudaGetSymbolAddress((void**)&cn,  g_cn);
    cudaGetSymbolAddress((void**)&qp,  g_q);
    cudaGetSymbolAddress((void**)&kvp, g_kv);
    cudaGetSymbolAddress((void**)&aT,  g_aT);

    constexpr int ATTN_SMEM = ATTN_SMEM_FLOATS * 4;
    cudaFuncSetAttribute(attn_kernel,
                         cudaFuncAttributeMaxDynamicSharedMemorySize, ATTN_SMEM);
    cudaFuncSetAttribute(gemm_mma<true, false>,
                         cudaFuncAttributeMaxDynamicSharedMemorySize, GEMM_SMEM_BYTES);
    cudaFuncSetAttribute(gemm_mma<false, false>,
                         cudaFuncAttributeMaxDynamicSharedMemorySize, GEMM_SMEM_BYTES);
    cudaFuncSetAttribute(gemm_mma<true, true>,
                         cudaFuncAttributeMaxDynamicSharedMemorySize, GEMM_SMEM_BYTES);

    // GroupNorm: x -> xnT (transposed [l][c]); ctx -> cn (natural [c][l])
    groupnorm_kernel<true ><<<NB * NG, 256>>>(x,   norm_w, norm_b, xnT);
    groupnorm_kernel<false><<<NB * NG, 256>>>(ctx, norm_w, norm_b, cn);

    // q[b,o,l] = q_w(o,c) * xnT(l,c)^T + q_b[o]
    gemm_mma<true, false><<<dim3(4, 4, NB), 256, GEMM_SMEM_BYTES>>>(
        q_w, 0, xnT, (long long)NL * NC, qp, (long long)NC * NL,
        q_b, nullptr, 0, NL, NC);

    // kv[b,c,o] = cn(c,l) * kv_w(o,l)^T + kv_b[o]
    gemm_mma<false, false><<<dim3(8, 4, NB), 256, GEMM_SMEM_BYTES>>>(
        cn, (long long)NC * NC, kv_w, 0, kvp, (long long)NC * 2 * NC,
        kv_b, nullptr, 0, 2 * NC, NC);

    // attention -> aT[b,l,c]
    attn_kernel<<<dim3(8, NB * 8), 256, ATTN_SMEM>>>(qp, kvp, aT);

    // out[b,o,l] = x + proj_w(o,c) * aT(l,c)^T + proj_b[o]
    gemm_mma<true, true><<<dim3(4, 4, NB), 256, GEMM_SMEM_BYTES>>>(
        proj_w, 0, aT, (long long)NL * NC, out, (long long)NC * NL,
        proj_b, x, (long long)NC * NL, NL, NC);
}

// round 7
// speedup vs baseline: 3.2778x; 1.9196x over previous
#include <cuda_runtime.h>
#include <math.h>
#include <stdint.h>

constexpr int NB = 32;      // batch
constexpr int NC = 512;     // channels
constexpr int NL = 512;     // length
constexpr int NG = 32;      // groups
constexpr float GEPS = 1e-5f;

// Scratch (static device globals: allocation-free, graph-safe)
__device__ float g_xnT[NB * NL * NC];           // x groupnorm, TRANSPOSED [l][c]
__device__ float g_cn [NB * NC * NC];           // ctx groupnorm, natural [c][l]
__device__ float g_q  [NB * NC * NL];           // q, [o][l]   (tf32-rounded)
__device__ float g_kv [NB * NC * 2 * NC];       // kv, [c][o]  (tf32-rounded)
__device__ float g_aT [NB * NL * NC];           // attn out, TRANSPOSED [l][c]

// ===========================================================================
// PTX helpers (plain sm_100-compatible: cp.async + mma.sync tf32)
// ===========================================================================
__device__ __forceinline__ uint32_t smem_u32(const void* p) {
    uint32_t a;
    asm("{ .reg .u64 t; cvta.to.shared.u64 t, %1; cvt.u32.u64 %0, t; }"
        : "=r"(a) : "l"(p));
    return a;
}
__device__ __forceinline__ void cp_async16(uint32_t dst, const float* src) {
    asm volatile("{ .reg .u64 g; cvta.to.global.u64 g, %1; "
                 "cp.async.cg.shared.global [%0], [g], 16; }"
                 :: "r"(dst), "l"(src) : "memory");
}
__device__ __forceinline__ uint32_t f2tf32(float f) {
    uint32_t u;
    asm("cvt.rna.tf32.f32 %0, %1;" : "=r"(u) : "f"(f));
    return u;
}
__device__ __forceinline__ void mma_tf32_16x8x8(
    float& c0, float& c1, float& c2, float& c3,
    uint32_t a0, uint32_t a1, uint32_t a2, uint32_t a3,
    uint32_t b0, uint32_t b1)
{
    asm volatile(
        "mma.sync.aligned.m16n8k8.row.col.f32.tf32.tf32.f32 "
        "{%0,%1,%2,%3}, {%4,%5,%6,%7}, {%8,%9}, {%0,%1,%2,%3};"
        : "+f"(c0), "+f"(c1), "+f"(c2), "+f"(c3)
        : "r"(a0), "r"(a1), "r"(a2), "r"(a3), "r"(b0), "r"(b1));
}
__device__ __forceinline__ float qmax(float v) {
    v = fmaxf(v, __shfl_xor_sync(0xffffffffu, v, 1));
    v = fmaxf(v, __shfl_xor_sync(0xffffffffu, v, 2));
    return v;
}
__device__ __forceinline__ float qsum(float v) {
    v += __shfl_xor_sync(0xffffffffu, v, 1);
    v += __shfl_xor_sync(0xffffffffu, v, 2);
    return v;
}

// ===========================================================================
// GroupNorm: one block per (batch, group). TRANS=true writes out[l][c] layout.
// ===========================================================================
template<bool TRANS>
__global__ __launch_bounds__(256) void groupnorm_kernel(
    const float* __restrict__ in, const float* __restrict__ w,
    const float* __restrict__ bia, float* __restrict__ out)
{
    const int bg = blockIdx.x;
    const int g = bg % NG;
    const float4* src = reinterpret_cast<const float4*>(in) + (size_t)bg * 2048;
    const int tid = threadIdx.x;

    float s = 0.f, ss = 0.f;
    float4 v[8];
#pragma unroll
    for (int i = 0; i < 8; i++) {
        v[i] = src[tid + i * 256];
        s  += v[i].x + v[i].y + v[i].z + v[i].w;
        ss += v[i].x * v[i].x + v[i].y * v[i].y + v[i].z * v[i].z + v[i].w * v[i].w;
    }
    __shared__ float red[2][8];
#pragma unroll
    for (int o = 16; o > 0; o >>= 1) {
        s  += __shfl_xor_sync(0xffffffffu, s, o);
        ss += __shfl_xor_sync(0xffffffffu, ss, o);
    }
    const int warp = tid >> 5, lane = tid & 31;
    if (lane == 0) { red[0][warp] = s; red[1][warp] = ss; }
    __syncthreads();
    if (warp == 0) {
        s = red[0][lane & 7]; ss = red[1][lane & 7];
#pragma unroll
        for (int o = 4; o > 0; o >>= 1) {
            s  += __shfl_xor_sync(0xffffffffu, s, o);
            ss += __shfl_xor_sync(0xffffffffu, ss, o);
        }
        if (lane == 0) { red[0][0] = s; red[1][0] = ss; }
    }
    __syncthreads();
    s = red[0][0]; ss = red[1][0];
    const float mu  = s * (1.f / 8192.f);
    const float var = ss * (1.f / 8192.f) - mu * mu;
    const float inv = rsqrtf(var + GEPS);

    if constexpr (!TRANS) {
        float4* dst = reinterpret_cast<float4*>(out) + (size_t)bg * 2048;
#pragma unroll
        for (int i = 0; i < 8; i++) {
            const int fi = tid + i * 256;
            const int c = g * 16 + (fi >> 7);
            const float sc = w[c] * inv;
            const float sh = bia[c] - mu * sc;
            float4 t = v[i];
            t.x = t.x * sc + sh; t.y = t.y * sc + sh;
            t.z = t.z * sc + sh; t.w = t.w * sc + sh;
            dst[fi] = t;
        }
    } else {
        __shared__ float st[16 * 516];
#pragma unroll
        for (int i = 0; i < 8; i++) {
            const int fi = tid + i * 256;
            const int cl = fi >> 7;               // local channel 0..15
            const int c = g * 16 + cl;
            const float sc = w[c] * inv;
            const float sh = bia[c] - mu * sc;
            float4 t = v[i];
            t.x = t.x * sc + sh; t.y = t.y * sc + sh;
            t.z = t.z * sc + sh; t.w = t.w * sc + sh;
            *reinterpret_cast<float4*>(&st[cl * 516 + (fi & 127) * 4]) = t;
        }
        __syncthreads();
        float* ob = out + (size_t)(bg >> 5) * NL * NC + g * 16;
        const int c4 = tid & 3;
#pragma unroll
        for (int r = 0; r < 8; r++) {
            const int l = (tid >> 2) + r * 64;
            float4 t;
            t.x = st[(c4 * 4 + 0) * 516 + l];
            t.y = st[(c4 * 4 + 1) * 516 + l];
            t.z = st[(c4 * 4 + 2) * 516 + l];
            t.w = st[(c4 * 4 + 3) * 516 + l];
            *reinterpret_cast<float4*>(ob + (size_t)l * NC + c4 * 4) = t;
        }
    }
}

// ===========================================================================
// tf32 mma.sync GEMM:  C[bz] tile(128x128) = A[M,K](K-major) * B[N,K](K-major)^T
// 8 warps (2x4), warp tile 64x32, m16n8k8, BK=32, cp.async double buffer.
// ROUND: tf32-round outputs (for tensors consumed by the attention MMA).
// ===========================================================================
constexpr int GEMM_SMEM_BYTES = 4 * 128 * 36 * 4;   // 73728

template<bool BIAS_ROW, bool HAS_RES, bool ROUND>
__global__ __launch_bounds__(256, 2) void gemm_mma(
    const float* __restrict__ A, long long sA,
    const float* __restrict__ B, long long sB,
    float* __restrict__ C, long long sC,
    const float* __restrict__ bias,
    const float* __restrict__ resid, long long sR,
    int N, int K)
{
    extern __shared__ float sm[];
    const uint32_t sb = smem_u32(sm);

    const int tid = threadIdx.x;
    const int lane = tid & 31, wid = tid >> 5;
    const int wm = wid >> 2, wn = wid & 3;           // 2 x 4 warp grid
    const int bz = blockIdx.z;
    const int m0 = blockIdx.y * 128, n0 = blockIdx.x * 128;
    const float* Ab = A + (size_t)sA * bz + (size_t)m0 * K;
    const float* Bb = B + (size_t)sB * bz + (size_t)n0 * K;

    auto loadTile = [&](uint32_t sbase, const float* g) {
#pragma unroll
        for (int i = 0; i < 4; i++) {
            const int idx = tid + i * 256;           // 0..1023
            const int row = idx >> 3, c16 = idx & 7;
            cp_async16(sbase + row * 144 + c16 * 16,
                       g + (size_t)row * K + c16 * 4);
        }
    };

    float acc[4][4][4];
#pragma unroll
    for (int a = 0; a < 4; a++)
#pragma unroll
        for (int b = 0; b < 4; b++)
#pragma unroll
            for (int c = 0; c < 4; c++) acc[a][b][c] = 0.f;

    const int NT = K >> 5;             // K chunks of 32

    loadTile(sb, Ab);
    loadTile(sb + 9216 * 4, Bb);
    asm volatile("cp.async.commit_group;" ::: "memory");

    const int r = lane >> 2, cq = lane & 3;

    for (int kt = 0; kt < NT; kt++) {
        asm volatile("cp.async.wait_group 0;" ::: "memory");
        __syncthreads();
        if (kt + 1 < NT) {
            const int s = (kt + 1) & 1;
            loadTile(sb + s * 4608 * 4, Ab + (kt + 1) * 32);
            loadTile(sb + (9216 + s * 4608) * 4, Bb + (kt + 1) * 32);
            asm volatile("cp.async.commit_group;" ::: "memory");
        }
        const int s = kt & 1;
        const float* a_ = sm + s * 4608 + (wm * 64 + r) * 36 + cq;
        const float* b_ = sm + 9216 + s * 4608 + (wn * 32 + r) * 36 + cq;
#pragma unroll
        for (int k8 = 0; k8 < 4; k8++) {
            uint32_t aF[4][4];
#pragma unroll
            for (int mt = 0; mt < 4; mt++) {
                const float* p = a_ + mt * 576 + k8 * 8;
                aF[mt][0] = f2tf32(p[0]);
                aF[mt][1] = f2tf32(p[288]);
                aF[mt][2] = f2tf32(p[4]);
                aF[mt][3] = f2tf32(p[292]);
            }
            uint32_t bF[4][2];
#pragma unroll
            for (int nt = 0; nt < 4; nt++) {
                const float* p = b_ + nt * 288 + k8 * 8;
                bF[nt][0] = f2tf32(p[0]);
                bF[nt][1] = f2tf32(p[4]);
            }
#pragma unroll
            for (int mt = 0; mt < 4; mt++)
#pragma unroll
                for (int nt = 0; nt < 4; nt++)
                    mma_tf32_16x8x8(acc[mt][nt][0], acc[mt][nt][1],
                                    acc[mt][nt][2], acc[mt][nt][3],
                                    aF[mt][0], aF[mt][1], aF[mt][2], aF[mt][3],
                                    bF[nt][0], bF[nt][1]);
        }
    }

    float* Cb = C + (size_t)sC * bz;
    const float* Rb = HAS_RES ? (resid + (size_t)sR * bz) : nullptr;
    const int m0w = m0 + wm * 64, n0w = n0 + wn * 32;
#pragma unroll
    for (int mt = 0; mt < 4; mt++) {
        const int r0 = m0w + mt * 16 + (lane >> 2);
        const float bm0 = BIAS_ROW ? __ldg(bias + r0) : 0.f;
        const float bm1 = BIAS_ROW ? __ldg(bias + r0 + 8) : 0.f;
#pragma unroll
        for (int nt = 0; nt < 4; nt++) {
            const int c0 = n0w + nt * 8 + (lane & 3) * 2;
            float bc0 = 0.f, bc1 = 0.f;
            if (!BIAS_ROW) { bc0 = __ldg(bias + c0); bc1 = __ldg(bias + c0 + 1); }
            float2 v0, v1;
            v0.x = acc[mt][nt][0] + (BIAS_ROW ? bm0 : bc0);
            v0.y = acc[mt][nt][1] + (BIAS_ROW ? bm0 : bc1);
            v1.x = acc[mt][nt][2] + (BIAS_ROW ? bm1 : bc0);
            v1.y = acc[mt][nt][3] + (BIAS_ROW ? bm1 : bc1);
            const size_t o0 = (size_t)r0 * N + c0;
            const size_t o1 = (size_t)(r0 + 8) * N + c0;
            if (HAS_RES) {
                const float2 q0 = *reinterpret_cast<const float2*>(Rb + o0);
                const float2 q1 = *reinterpret_cast<const float2*>(Rb + o1);
                v0.x += q0.x; v0.y += q0.y;
                v1.x += q1.x; v1.y += q1.y;
            }
            if (ROUND) {
                v0.x = __uint_as_float(f2tf32(v0.x));
                v0.y = __uint_as_float(f2tf32(v0.y));
                v1.x = __uint_as_float(f2tf32(v1.x));
                v1.y = __uint_as_float(f2tf32(v1.y));
            }
            *reinterpret_cast<float2*>(Cb + o0) = v0;
            *reinterpret_cast<float2*>(Cb + o1) = v1;
        }
    }
}

// ===========================================================================
// Fused attention on mma.sync tf32, fp32 online softmax.
// grid = (L/128 t-tiles, B*NH), block = 256 (8 warps x 16 t-rows each).
// q/kv are tf32-pre-rounded in gmem -> fragments load raw bits (no cvt).
// s processed in 8 chunks of 64, cp.async double-buffered K/V.
// Smem float offsets (total 35328 floats = 141312 bytes):
//   Qs [128][68]   @ 0      (t, d) pre-scaled by 1/8
//   Ks [2][64][72] @ 8704   (d, s-chunk)
//   Vs [2][64][68] @ 17920  (d, s-chunk)
//   Ps [128][68]   @ 26624  (t, s-chunk) warp-private rows
// ===========================================================================
constexpr int AK = 8704;
constexpr int AV = AK + 2 * 64 * 72;      // 17920
constexpr int AP = AV + 2 * 64 * 68;      // 26624
constexpr int ATT_FLOATS = AP + 128 * 68; // 35328 -> 141312 bytes

__global__ __launch_bounds__(256) void attn_mma(
    const float* __restrict__ q, const float* __restrict__ kv,
    float* __restrict__ outaT)
{
    extern __shared__ float smf[];
    const uint32_t sb = smem_u32(smf);
    const uint32_t* sp = reinterpret_cast<const uint32_t*>(smf);
    const int tid = threadIdx.x, lane = tid & 31, w = tid >> 5;
    const int t0 = blockIdx.x * 128;
    const int bh = blockIdx.y, b = bh >> 3, h = bh & 7;
    const int r = lane >> 2, c = lane & 3;

    // ---- load Q tile: gmem [d][t] -> smem [t][68] (scaled by 1/8, exact) ----
    {
        const float* qb = q + ((size_t)b * NC + h * 64) * NL + t0;
        const int d = tid >> 2, tq = tid & 3;
#pragma unroll
        for (int rr = 0; rr < 8; rr++) {
            const int t4 = tq + rr * 4;
            float4 v = *reinterpret_cast<const float4*>(qb + (size_t)d * NL + t4 * 4);
            smf[(t4 * 4 + 0) * 68 + d] = v.x * 0.125f;
            smf[(t4 * 4 + 1) * 68 + d] = v.y * 0.125f;
            smf[(t4 * 4 + 2) * 68 + d] = v.z * 0.125f;
            smf[(t4 * 4 + 3) * 68 + d] = v.w * 0.125f;
        }
    }

    const float* kvb = kv + (size_t)b * NC * 1024;
    // chunk = 64 s values. Each d-row needs 64 floats = 16 float4.
    auto loadKV = [&](int sc, int buf) {
#pragma unroll
        for (int i = 0; i < 4; i++) {
            const int idx = tid + i * 256;               // 0..1023
            const int row = idx >> 4, s16 = idx & 15;    // d row, float4 col
            const int ck = 32 * h + (row >> 1);
            const int ob = (row & 1) * 512;
            const float* srcK = kvb + (size_t)ck * 1024 + ob + sc * 64 + s16 * 4;
            cp_async16(sb + (uint32_t)(AK + buf * 64 * 72 + row * 72) * 4 + s16 * 16,
                       srcK);
            cp_async16(sb + (uint32_t)(AV + buf * 64 * 68 + row * 68) * 4 + s16 * 16,
                       srcK + 256 * 1024);
        }
    };

    loadKV(0, 0);
    asm volatile("cp.async.commit_group;" ::: "memory");

    float m0 = -1e30f, m1 = -1e30f, l0 = 0.f, l1 = 0.f;
    float O[8][4];
#pragma unroll
    for (int j = 0; j < 8; j++)
#pragma unroll
        for (int k = 0; k < 4; k++) O[j][k] = 0.f;

    const int tb = w * 16;

    for (int sc = 0; sc < 8; sc++) {
        asm volatile("cp.async.wait_group 0;" ::: "memory");
        __syncthreads();
        if (sc < 7) {
            loadKV(sc + 1, (sc + 1) & 1);
            asm volatile("cp.async.commit_group;" ::: "memory");
        }
        const int kb = AK + (sc & 1) * 64 * 72;
        const int vb = AV + (sc & 1) * 64 * 68;

        // ---- S = Q^T K  (warp: 16t x 64s) ----
        float S[8][4];
#pragma unroll
        for (int j = 0; j < 8; j++)
#pragma unroll
            for (int k = 0; k < 4; k++) S[j][k] = 0.f;

#pragma unroll
        for (int k8 = 0; k8 < 8; k8++) {
            const uint32_t a0 = sp[(tb + r) * 68 + k8 * 8 + c];
            const uint32_t a1 = sp[(tb + r + 8) * 68 + k8 * 8 + c];
            const uint32_t a2 = sp[(tb + r) * 68 + k8 * 8 + c + 4];
            const uint32_t a3 = sp[(tb + r + 8) * 68 + k8 * 8 + c + 4];
#pragma unroll
            for (int j = 0; j < 8; j++) {
                const uint32_t b0 = sp[kb + (k8 * 8 + c) * 72 + j * 8 + r];
                const uint32_t b1 = sp[kb + (k8 * 8 + c + 4) * 72 + j * 8 + r];
                mma_tf32_16x8x8(S[j][0], S[j][1], S[j][2], S[j][3],
                                a0, a1, a2, a3, b0, b1);
            }
        }

        // ---- online softmax (rows warp-private; quad reductions only) ----
        float mx0 = -1e30f, mx1 = -1e30f;
#pragma unroll
        for (int j = 0; j < 8; j++) {
            mx0 = fmaxf(mx0, fmaxf(S[j][0], S[j][1]));
            mx1 = fmaxf(mx1, fmaxf(S[j][2], S[j][3]));
        }
        mx0 = qmax(mx0); mx1 = qmax(mx1);
        const float mn0 = fmaxf(m0, mx0), mn1 = fmaxf(m1, mx1);
        const float al0 = __expf(m0 - mn0), al1 = __expf(m1 - mn1);
        m0 = mn0; m1 = mn1;

        float rs0 = 0.f, rs1 = 0.f;
        float* Pw = smf + AP;
#pragma unroll
        for (int j = 0; j < 8; j++) {
            const float p0 = __expf(S[j][0] - mn0);
            const float p1 = __expf(S[j][1] - mn0);
            const float p2 = __expf(S[j][2] - mn1);
            const float p3 = __expf(S[j][3] - mn1);
            rs0 += p0 + p1; rs1 += p2 + p3;
            float2 u0, u1;
            u0.x = __uint_as_float(f2tf32(p0));
            u0.y = __uint_as_float(f2tf32(p1));
            u1.x = __uint_as_float(f2tf32(p2));
            u1.y = __uint_as_float(f2tf32(p3));
            *reinterpret_cast<float2*>(&Pw[(tb + r) * 68 + j * 8 + 2 * c]) = u0;
            *reinterpret_cast<float2*>(&Pw[(tb + r + 8) * 68 + j * 8 + 2 * c]) = u1;
        }
        rs0 = qsum(rs0); rs1 = qsum(rs1);
        l0 = l0 * al0 + rs0;
        l1 = l1 * al1 + rs1;
#pragma unroll
        for (int j = 0; j < 8; j++) {
            O[j][0] *= al0; O[j][1] *= al0;
            O[j][2] *= al1; O[j][3] *= al1;
        }
        __syncwarp();

        // ---- O += P V^T  (warp: 16t x 64d, K = 64 s) ----
#pragma unroll
        for (int ks = 0; ks < 8; ks++) {
            const uint32_t a0 = sp[AP + (tb + r) * 68 + ks * 8 + c];
            const uint32_t a1 = sp[AP + (tb + r + 8) * 68 + ks * 8 + c];
            const uint32_t a2 = sp[AP + (tb + r) * 68 + ks * 8 + c + 4];
            const uint32_t a3 = sp[AP + (tb + r + 8) * 68 + ks * 8 + c + 4];
#pragma unroll
            for (int j = 0; j < 8; j++) {
                const uint32_t b0 = sp[vb + (j * 8 + r) * 68 + ks * 8 + c];
                const uint32_t b1 = sp[vb + (j * 8 + r) * 68 + ks * 8 + c + 4];
                mma_tf32_16x8x8(O[j][0], O[j][1], O[j][2], O[j][3],
                                a0, a1, a2, a3, b0, b1);
            }
        }
    }

    // ---- finalize + store transposed: aT[b][l][h*64 + d] ----
    const float i0 = 1.f / l0, i1 = 1.f / l1;
    float* ab = outaT + ((size_t)b * NL + t0 + tb) * NC + h * 64;
#pragma unroll
    for (int j = 0; j < 8; j++) {
        float2 u;
        u.x = O[j][0] * i0; u.y = O[j][1] * i0;
        *reinterpret_cast<float2*>(ab + (size_t)r * NC + j * 8 + 2 * c) = u;
        u.x = O[j][2] * i1; u.y = O[j][3] * i1;
        *reinterpret_cast<float2*>(ab + (size_t)(r + 8) * NC + j * 8 + 2 * c) = u;
    }
}

// ===========================================================================
extern "C" void kernel_launch(void* const* d_in, const int* in_sizes, int n_in,
                              void* d_out, int out_size)
{
    const float* x      = (const float*)d_in[0];
    const float* ctx    = (const float*)d_in[1];
    const float* norm_w = (const float*)d_in[2];
    const float* norm_b = (const float*)d_in[3];
    const float* q_w    = (const float*)d_in[4];
    const float* q_b    = (const float*)d_in[5];
    const float* kv_w   = (const float*)d_in[6];
    const float* kv_b   = (const float*)d_in[7];
    const float* proj_w = (const float*)d_in[8];
    const float* proj_b = (const float*)d_in[9];
    float* out = (float*)d_out;

    float *xnT, *cn, *qp, *kvp, *aT;
    cudaGetSymbolAddress((void**)&xnT, g_xnT);
    cudaGetSymbolAddress((void**)&cn,  g_cn);
    cudaGetSymbolAddress((void**)&qp,  g_q);
    cudaGetSymbolAddress((void**)&kvp, g_kv);
    cudaGetSymbolAddress((void**)&aT,  g_aT);

    constexpr int ATTN_SMEM = ATT_FLOATS * 4;     // 141312
    cudaFuncSetAttribute(attn_mma,
                         cudaFuncAttributeMaxDynamicSharedMemorySize, ATTN_SMEM);
    cudaFuncSetAttribute(gemm_mma<true, false, true>,
                         cudaFuncAttributeMaxDynamicSharedMemorySize, GEMM_SMEM_BYTES);
    cudaFuncSetAttribute(gemm_mma<false, false, true>,
                         cudaFuncAttributeMaxDynamicSharedMemorySize, GEMM_SMEM_BYTES);
    cudaFuncSetAttribute(gemm_mma<true, true, false>,
                         cudaFuncAttributeMaxDynamicSharedMemorySize, GEMM_SMEM_BYTES);

    // GroupNorm: x -> xnT (transposed [l][c]); ctx -> cn (natural [c][l])
    groupnorm_kernel<true ><<<NB * NG, 256>>>(x,   norm_w, norm_b, xnT);
    groupnorm_kernel<false><<<NB * NG, 256>>>(ctx, norm_w, norm_b, cn);

    // q[b,o,l] = q_w(o,c) * xnT(l,c)^T + q_b[o]   (tf32-rounded output)
    gemm_mma<true, false, true><<<dim3(4, 4, NB), 256, GEMM_SMEM_BYTES>>>(
        q_w, 0, xnT, (long long)NL * NC, qp, (long long)NC * NL,
        q_b, nullptr, 0, NL, NC);

    // kv[b,c,o] = cn(c,l) * kv_w(o,l)^T + kv_b[o]  (tf32-rounded output)
    gemm_mma<false, false, true><<<dim3(8, 4, NB), 256, GEMM_SMEM_BYTES>>>(
        cn, (long long)NC * NC, kv_w, 0, kvp, (long long)NC * 2 * NC,
        kv_b, nullptr, 0, 2 * NC, NC);

    // attention -> aT[b,l,c]
    attn_mma<<<dim3(4, NB * 8), 256, ATTN_SMEM>>>(qp, kvp, aT);

    // out[b,o,l] = x + proj_w(o,c) * aT(l,c)^T + proj_b[o]
    gemm_mma<true, true, false><<<dim3(4, 4, NB), 256, GEMM_SMEM_BYTES>>>(
        proj_w, 0, aT, (long long)NL * NC, out, (long long)NC * NL,
        proj_b, x, (long long)NC * NL, NL, NC);
}

// round 8
// speedup vs baseline: 7.3899x; 2.2545x over previous
#include <cuda_runtime.h>
#include <cuda_bf16.h>
#include <math.h>
#include <stdint.h>

constexpr int NB = 32;      // batch
constexpr int NC = 512;     // channels
constexpr int NL = 512;     // length
constexpr int NG = 32;      // groups
constexpr float GEPS = 1e-5f;

// Scratch (static device globals: allocation-free, graph-safe) — bf16
__device__ __nv_bfloat16 g_xnT[NB * NL * NC];     // GN(x), TRANSPOSED [l][c]
__device__ __nv_bfloat16 g_cn [NB * NC * NC];     // GN(ctx), natural [c][l]
__device__ __nv_bfloat16 g_q  [NB * NL * NC];     // qT [l][o], pre-scaled by 1/8
__device__ __nv_bfloat16 g_kv [NB * NC * 2 * NC]; // kv [c][o]
__device__ __nv_bfloat16 g_aT [NB * NL * NC];     // attn out, TRANSPOSED [l][c]
__device__ __nv_bfloat16 g_qw [NC * NC];          // bf16 weights
__device__ __nv_bfloat16 g_kvw[2 * NC * NC];
__device__ __nv_bfloat16 g_pw [NC * NC];

// ===========================================================================
// PTX helpers (plain sm_100-compatible)
// ===========================================================================
__device__ __forceinline__ uint32_t smem_u32(const void* p) {
    uint32_t a;
    asm("{ .reg .u64 t; cvta.to.shared.u64 t, %1; cvt.u32.u64 %0, t; }"
        : "=r"(a) : "l"(p));
    return a;
}
__device__ __forceinline__ void cp_async16(uint32_t dst, const void* src) {
    asm volatile("{ .reg .u64 g; cvta.to.global.u64 g, %1; "
                 "cp.async.cg.shared.global [%0], [g], 16; }"
                 :: "r"(dst), "l"(src) : "memory");
}
__device__ __forceinline__ void ldsm4(uint32_t* r, uint32_t a) {
    asm volatile("ldmatrix.sync.aligned.m8n8.x4.shared.b16 {%0,%1,%2,%3}, [%4];"
                 : "=r"(r[0]), "=r"(r[1]), "=r"(r[2]), "=r"(r[3]) : "r"(a));
}
__device__ __forceinline__ void ldsm4t(uint32_t* r, uint32_t a) {
    asm volatile("ldmatrix.sync.aligned.m8n8.x4.trans.shared.b16 {%0,%1,%2,%3}, [%4];"
                 : "=r"(r[0]), "=r"(r[1]), "=r"(r[2]), "=r"(r[3]) : "r"(a));
}
__device__ __forceinline__ void mma_bf16(float* c, const uint32_t* a, const uint32_t* b) {
    asm volatile(
        "mma.sync.aligned.m16n8k16.row.col.f32.bf16.bf16.f32 "
        "{%0,%1,%2,%3}, {%4,%5,%6,%7}, {%8,%9}, {%0,%1,%2,%3};"
        : "+f"(c[0]), "+f"(c[1]), "+f"(c[2]), "+f"(c[3])
        : "r"(a[0]), "r"(a[1]), "r"(a[2]), "r"(a[3]), "r"(b[0]), "r"(b[1]));
}
__device__ __forceinline__ uint32_t packbf(float lo, float hi) {
    __nv_bfloat162 h = __floats2bfloat162_rn(lo, hi);
    return *reinterpret_cast<uint32_t*>(&h);
}
__device__ __forceinline__ float qmax(float v) {
    v = fmaxf(v, __shfl_xor_sync(0xffffffffu, v, 1));
    v = fmaxf(v, __shfl_xor_sync(0xffffffffu, v, 2));
    return v;
}
__device__ __forceinline__ float qsum(float v) {
    v += __shfl_xor_sync(0xffffffffu, v, 1);
    v += __shfl_xor_sync(0xffffffffu, v, 2);
    return v;
}

// ===========================================================================
// fp32 -> bf16 weight conversion (1M elements total, ~trivial)
// ===========================================================================
__global__ __launch_bounds__(256) void cvt_bf16_kernel(
    const float* __restrict__ s, __nv_bfloat16* __restrict__ d, int n4)
{
    const int i = blockIdx.x * 256 + threadIdx.x;
    if (i >= n4) return;
    const float4 v = reinterpret_cast<const float4*>(s)[i];
    uint2 u;
    u.x = packbf(v.x, v.y);
    u.y = packbf(v.z, v.w);
    reinterpret_cast<uint2*>(d)[i] = u;
}

// ===========================================================================
// GroupNorm: one block per (batch, group). bf16 output.
// TRANS=true writes out[l][c] layout (for xnT).
// ===========================================================================
template<bool TRANS>
__global__ __launch_bounds__(256) void groupnorm_kernel(
    const float* __restrict__ in, const float* __restrict__ w,
    const float* __restrict__ bia, __nv_bfloat16* __restrict__ out)
{
    const int bg = blockIdx.x;
    const int g = bg % NG;
    const float4* src = reinterpret_cast<const float4*>(in) + (size_t)bg * 2048;
    const int tid = threadIdx.x;

    float s = 0.f, ss = 0.f;
    float4 v[8];
#pragma unroll
    for (int i = 0; i < 8; i++) {
        v[i] = src[tid + i * 256];
        s  += v[i].x + v[i].y + v[i].z + v[i].w;
        ss += v[i].x * v[i].x + v[i].y * v[i].y + v[i].z * v[i].z + v[i].w * v[i].w;
    }
    __shared__ float red[2][8];
#pragma unroll
    for (int o = 16; o > 0; o >>= 1) {
        s  += __shfl_xor_sync(0xffffffffu, s, o);
        ss += __shfl_xor_sync(0xffffffffu, ss, o);
    }
    const int warp = tid >> 5, lane = tid & 31;
    if (lane == 0) { red[0][warp] = s; red[1][warp] = ss; }
    __syncthreads();
    if (warp == 0) {
        s = red[0][lane & 7]; ss = red[1][lane & 7];
#pragma unroll
        for (int o = 4; o > 0; o >>= 1) {
            s  += __shfl_xor_sync(0xffffffffu, s, o);
            ss += __shfl_xor_sync(0xffffffffu, ss, o);
        }
        if (lane == 0) { red[0][0] = s; red[1][0] = ss; }
    }
    __syncthreads();
    s = red[0][0]; ss = red[1][0];
    const float mu  = s * (1.f / 8192.f);
    const float var = ss * (1.f / 8192.f) - mu * mu;
    const float inv = rsqrtf(var + GEPS);

    if constexpr (!TRANS) {
        uint2* dst = reinterpret_cast<uint2*>(out) + (size_t)bg * 2048;
#pragma unroll
        for (int i = 0; i < 8; i++) {
            const int fi = tid + i * 256;
            const int c = g * 16 + (fi >> 7);
            const float sc = w[c] * inv;
            const float sh = bia[c] - mu * sc;
            float4 t = v[i];
            uint2 u;
            u.x = packbf(t.x * sc + sh, t.y * sc + sh);
            u.y = packbf(t.z * sc + sh, t.w * sc + sh);
            dst[fi] = u;
        }
    } else {
        __shared__ float st[16 * 516];
#pragma unroll
        for (int i = 0; i < 8; i++) {
            const int fi = tid + i * 256;
            const int cl = fi >> 7;               // local channel 0..15
            const int c = g * 16 + cl;
            const float sc = w[c] * inv;
            const float sh = bia[c] - mu * sc;
            float4 t = v[i];
            t.x = t.x * sc + sh; t.y = t.y * sc + sh;
            t.z = t.z * sc + sh; t.w = t.w * sc + sh;
            *reinterpret_cast<float4*>(&st[cl * 516 + (fi & 127) * 4]) = t;
        }
        __syncthreads();
        __nv_bfloat16* ob = out + (size_t)(bg >> 5) * NL * NC + g * 16;
        const int c4 = tid & 3;
#pragma unroll
        for (int r = 0; r < 8; r++) {
            const int l = (tid >> 2) + r * 64;
            uint2 u;
            u.x = packbf(st[(c4 * 4 + 0) * 516 + l], st[(c4 * 4 + 1) * 516 + l]);
            u.y = packbf(st[(c4 * 4 + 2) * 516 + l], st[(c4 * 4 + 3) * 516 + l]);
            *reinterpret_cast<uint2*>(ob + (size_t)l * NC + c4 * 4) = u;
        }
    }
}

// ===========================================================================
// bf16 mma.sync GEMM: C[bz](128x128) = A[M,K](K-major) * B[N,K](K-major)^T
// 8 warps (2x4), warp tile 64x32, m16n8k16, BK=64, cp.async double buffer.
// smem rows: 128B (64 bf16), chunk j XOR-swizzled with (row&7).
// MODE 0: fp32 out + bias-row + residual; 1: bf16 out + bias-col;
// MODE 2: bf16 out = (acc+bias-col)*0.125 (for q).
// ===========================================================================
constexpr int GEMM_SMEM = 65536;   // A0,A1,B0,B1 tiles of 16KB

template<int MODE>
__global__ __launch_bounds__(256, 2) void gemm_bf16(
    const __nv_bfloat16* __restrict__ A, long long sA,
    const __nv_bfloat16* __restrict__ B, long long sB,
    void* __restrict__ Cv, long long sC,
    const float* __restrict__ bias,
    const float* __restrict__ resid, long long sR,
    int N, int K)
{
    extern __shared__ char smc[];
    const uint32_t sb = smem_u32(smc);
    const int tid = threadIdx.x, lane = tid & 31, wid = tid >> 5;
    const int wm = wid >> 2, wn = wid & 3;
    const int bz = blockIdx.z;
    const int m0 = blockIdx.y * 128, n0 = blockIdx.x * 128;
    const __nv_bfloat16* Ab = A + (size_t)sA * bz + (size_t)m0 * K;
    const __nv_bfloat16* Bb = B + (size_t)sB * bz + (size_t)n0 * K;

    auto loadTile = [&](uint32_t sbase, const __nv_bfloat16* gp) {
#pragma unroll
        for (int i = 0; i < 4; i++) {
            const int idx = tid + i * 256;
            const int row = idx >> 3, j = idx & 7;
            cp_async16(sbase + row * 128 + ((j ^ (row & 7)) << 4),
                       gp + (size_t)row * K + j * 8);
        }
    };

    float acc[4][4][4];
#pragma unroll
    for (int a = 0; a < 4; a++)
#pragma unroll
        for (int b = 0; b < 4; b++)
#pragma unroll
            for (int c = 0; c < 4; c++) acc[a][b][c] = 0.f;

    const int NT = K >> 6;
    loadTile(sb, Ab);
    loadTile(sb + 32768, Bb);
    asm volatile("cp.async.commit_group;" ::: "memory");

    const int g = lane >> 2, tq = lane & 3;
    const int arow = (lane & 7) + ((lane >> 3) & 1) * 8;   // A: mat&1 row-half
    const int aoff = lane >> 4;                            // A: mat>>1 chunk
    const int brow = (lane & 7) + ((lane >> 4) & 1) * 8;   // B: mat>>1 row-half
    const int boff = (lane >> 3) & 1;                      // B: mat&1 chunk

    for (int kt = 0; kt < NT; kt++) {
        asm volatile("cp.async.wait_group 0;" ::: "memory");
        __syncthreads();
        if (kt + 1 < NT) {
            const int s = (kt + 1) & 1;
            loadTile(sb + s * 16384, Ab + (kt + 1) * 64);
            loadTile(sb + 32768 + s * 16384, Bb + (kt + 1) * 64);
            asm volatile("cp.async.commit_group;" ::: "memory");
        }
        const uint32_t ab = sb + (kt & 1) * 16384;
        const uint32_t bb = sb + 32768 + (kt & 1) * 16384;
#pragma unroll
        for (int kk = 0; kk < 4; kk++) {
            uint32_t af[4][4];
#pragma unroll
            for (int mt = 0; mt < 4; mt++) {
                const int row = wm * 64 + mt * 16 + arow;
                ldsm4(af[mt], ab + row * 128 + (((kk * 2 + aoff) ^ (row & 7)) << 4));
            }
            uint32_t bfr[4][2];
#pragma unroll
            for (int bt = 0; bt < 2; bt++) {
                const int row = wn * 32 + bt * 16 + brow;
                uint32_t r[4];
                ldsm4(r, bb + row * 128 + (((kk * 2 + boff) ^ (row & 7)) << 4));
                bfr[bt * 2][0] = r[0];     bfr[bt * 2][1] = r[1];
                bfr[bt * 2 + 1][0] = r[2]; bfr[bt * 2 + 1][1] = r[3];
            }
#pragma unroll
            for (int mt = 0; mt < 4; mt++)
#pragma unroll
                for (int nt = 0; nt < 4; nt++)
                    mma_bf16(acc[mt][nt], af[mt], bfr[nt]);
        }
    }

    const int m0w = m0 + wm * 64, n0w = n0 + wn * 32;
    if constexpr (MODE == 0) {
        float* C = reinterpret_cast<float*>(Cv) + (size_t)sC * bz;
        const float* R = resid + (size_t)sR * bz;
#pragma unroll
        for (int mt = 0; mt < 4; mt++) {
            const int r0 = m0w + mt * 16 + g;
            const float bm0 = __ldg(bias + r0), bm1 = __ldg(bias + r0 + 8);
#pragma unroll
            for (int nt = 0; nt < 4; nt++) {
                const int c0 = n0w + nt * 8 + tq * 2;
                const size_t o0 = (size_t)r0 * N + c0;
                const size_t o1 = (size_t)(r0 + 8) * N + c0;
                const float2 q0 = *reinterpret_cast<const float2*>(R + o0);
                const float2 q1 = *reinterpret_cast<const float2*>(R + o1);
                float2 v0, v1;
                v0.x = acc[mt][nt][0] + bm0 + q0.x;
                v0.y = acc[mt][nt][1] + bm0 + q0.y;
                v1.x = acc[mt][nt][2] + bm1 + q1.x;
                v1.y = acc[mt][nt][3] + bm1 + q1.y;
                *reinterpret_cast<float2*>(C + o0) = v0;
                *reinterpret_cast<float2*>(C + o1) = v1;
            }
        }
    } else {
        __nv_bfloat16* C = reinterpret_cast<__nv_bfloat16*>(Cv) + (size_t)sC * bz;
        const float sc = (MODE == 2) ? 0.125f : 1.f;
#pragma unroll
        for (int mt = 0; mt < 4; mt++) {
            const int r0 = m0w + mt * 16 + g;
#pragma unroll
            for (int nt = 0; nt < 4; nt++) {
                const int c0 = n0w + nt * 8 + tq * 2;
                const float bc0 = __ldg(bias + c0), bc1 = __ldg(bias + c0 + 1);
                *reinterpret_cast<uint32_t*>(C + (size_t)r0 * N + c0) =
                    packbf((acc[mt][nt][0] + bc0) * sc, (acc[mt][nt][1] + bc1) * sc);
                *reinterpret_cast<uint32_t*>(C + (size_t)(r0 + 8) * N + c0) =
                    packbf((acc[mt][nt][2] + bc0) * sc, (acc[mt][nt][3] + bc1) * sc);
            }
        }
    }
}

// ===========================================================================
// Fused attention on mma.sync bf16, fp32 online softmax.
// grid = (L/128 t-tiles, B*NH), block = 256 (8 warps x 16 warp-private rows).
// smem (64KB): Q [128][64] @0, K [2][64][64] @16384, V [2][64][64] @32768,
//              P [128][64] @49152 — all bf16, 128B rows, XOR-swizzled chunks.
// ===========================================================================
constexpr int ATTN_SMEM = 65536;

__global__ __launch_bounds__(256, 2) void attn_bf16(
    const __nv_bfloat16* __restrict__ q, const __nv_bfloat16* __restrict__ kv,
    __nv_bfloat16* __restrict__ outaT)
{
    extern __shared__ char smc[];
    const uint32_t sb = smem_u32(smc);
    const int tid = threadIdx.x, lane = tid & 31, w = tid >> 5;
    const int t0 = blockIdx.x * 128;
    const int bh = blockIdx.y, b = bh >> 3, h = bh & 7;
    const int g = lane >> 2, tq = lane & 3;
    const int tb = w * 16;

    // Q tile: qT[b*NL + t0 + t][h*64 + d]  (rows t, d contiguous)
    {
        const __nv_bfloat16* qb = q + ((size_t)b * NL + t0) * NC + h * 64;
#pragma unroll
        for (int i = 0; i < 4; i++) {
            const int idx = tid + i * 256;
            const int t = idx >> 3, j = idx & 7;
            cp_async16(sb + t * 128 + ((j ^ (t & 7)) << 4),
                       qb + (size_t)t * NC + j * 8);
        }
    }
    const __nv_bfloat16* kvb = kv + (size_t)b * NC * 1024;
    auto loadKV = [&](int sc, int buf) {
#pragma unroll
        for (int i = 0; i < 2; i++) {
            const int idx = tid + i * 256;
            const int d = idx >> 3, j = idx & 7;
            const int ck = 32 * h + (d >> 1);
            const int ob = (d & 1) * 512 + sc * 64 + j * 8;
            const __nv_bfloat16* srcK = kvb + (size_t)ck * 1024 + ob;
            const uint32_t soff = d * 128 + ((j ^ (d & 7)) << 4);
            cp_async16(sb + 16384 + buf * 8192 + soff, srcK);
            cp_async16(sb + 32768 + buf * 8192 + soff, srcK + 256 * 1024);
        }
    };
    loadKV(0, 0);
    asm volatile("cp.async.commit_group;" ::: "memory");

    float m0 = -1e30f, m1 = -1e30f, l0 = 0.f, l1 = 0.f;
    float O[8][4];
#pragma unroll
    for (int j = 0; j < 8; j++)
#pragma unroll
        for (int k = 0; k < 4; k++) O[j][k] = 0.f;

    const int arow = tb + (lane & 7) + ((lane >> 3) & 1) * 8; // A frag rows (Q/P)
    const int aoff = lane >> 4;
    const int ktrow = (lane & 7) + ((lane >> 3) & 1) * 8;     // K-trans: d rows
    const int ktoff = lane >> 4;                               // K-trans: s chunk
    const int vrow = (lane & 7) + ((lane >> 4) & 1) * 8;      // V: d row-half
    const int voff = (lane >> 3) & 1;                          // V: s chunk

    for (int sc = 0; sc < 8; sc++) {
        asm volatile("cp.async.wait_group 0;" ::: "memory");
        __syncthreads();
        if (sc < 7) {
            loadKV(sc + 1, (sc + 1) & 1);
            asm volatile("cp.async.commit_group;" ::: "memory");
        }
        const uint32_t kbK = sb + 16384 + (sc & 1) * 8192;
        const uint32_t kbV = sb + 32768 + (sc & 1) * 8192;

        // ---- S = Q K^T  (warp: 16t x 64s; k = d over 4 k16 groups) ----
        float S[8][4];
#pragma unroll
        for (int j = 0; j < 8; j++)
#pragma unroll
            for (int k = 0; k < 4; k++) S[j][k] = 0.f;

#pragma unroll
        for (int kk = 0; kk < 4; kk++) {
            uint32_t af[4];
            ldsm4(af, sb + arow * 128 + (((kk * 2 + aoff) ^ (arow & 7)) << 4));
            uint32_t bfr[8][2];
#pragma unroll
            for (int st = 0; st < 4; st++) {
                const int drow = kk * 16 + ktrow;
                uint32_t r[4];
                ldsm4t(r, kbK + drow * 128 + (((st * 2 + ktoff) ^ (drow & 7)) << 4));
                bfr[st * 2][0] = r[0];     bfr[st * 2][1] = r[1];
                bfr[st * 2 + 1][0] = r[2]; bfr[st * 2 + 1][1] = r[3];
            }
#pragma unroll
            for (int j = 0; j < 8; j++) mma_bf16(S[j], af, bfr[j]);
        }

        // ---- online softmax (warp-private rows; quad reductions only) ----
        float mx0 = -1e30f, mx1 = -1e30f;
#pragma unroll
        for (int j = 0; j < 8; j++) {
            mx0 = fmaxf(mx0, fmaxf(S[j][0], S[j][1]));
            mx1 = fmaxf(mx1, fmaxf(S[j][2], S[j][3]));
        }
        mx0 = qmax(mx0); mx1 = qmax(mx1);
        const float mn0 = fmaxf(m0, mx0), mn1 = fmaxf(m1, mx1);
        const float al0 = __expf(m0 - mn0), al1 = __expf(m1 - mn1);
        m0 = mn0; m1 = mn1;

        float rs0 = 0.f, rs1 = 0.f;
        const int t1r = tb + g, t2r = tb + g + 8;
        char* P1 = smc + 49152 + t1r * 128 + 4 * tq;
        char* P2 = smc + 49152 + t2r * 128 + 4 * tq;
        const int tsw = t1r & 7;
#pragma unroll
        for (int j = 0; j < 8; j++) {
            const float p0 = __expf(S[j][0] - mn0);
            const float p1 = __expf(S[j][1] - mn0);
            const float p2 = __expf(S[j][2] - mn1);
            const float p3 = __expf(S[j][3] - mn1);
            rs0 += p0 + p1; rs1 += p2 + p3;
            *reinterpret_cast<uint32_t*>(P1 + ((j ^ tsw) << 4)) = packbf(p0, p1);
            *reinterpret_cast<uint32_t*>(P2 + ((j ^ tsw) << 4)) = packbf(p2, p3);
        }
        rs0 = qsum(rs0); rs1 = qsum(rs1);
        l0 = l0 * al0 + rs0;
        l1 = l1 * al1 + rs1;
#pragma unroll
        for (int j = 0; j < 8; j++) {
            O[j][0] *= al0; O[j][1] *= al0;
            O[j][2] *= al1; O[j][3] *= al1;
        }
        __syncwarp();

        // ---- O += P V  (warp: 16t x 64d; k = s over 4 k16 groups) ----
        const uint32_t pb = sb + 49152;
#pragma unroll
        for (int kk = 0; kk < 4; kk++) {
            uint32_t af[4];
            ldsm4(af, pb + arow * 128 + (((kk * 2 + aoff) ^ (arow & 7)) << 4));
            uint32_t bfr[8][2];
#pragma unroll
            for (int dt = 0; dt < 4; dt++) {
                const int row = dt * 16 + vrow;
                uint32_t r[4];
                ldsm4(r, kbV + row * 128 + (((kk * 2 + voff) ^ (row & 7)) << 4));
                bfr[dt * 2][0] = r[0];     bfr[dt * 2][1] = r[1];
                bfr[dt * 2 + 1][0] = r[2]; bfr[dt * 2 + 1][1] = r[3];
            }
#pragma unroll
            for (int j = 0; j < 8; j++) mma_bf16(O[j], af, bfr[j]);
        }
    }

    // ---- finalize + store: aT[b][t0+t][h*64 + d] (bf16 pairs) ----
    const float i0 = 1.f / l0, i1 = 1.f / l1;
    __nv_bfloat16* ab = outaT + ((size_t)b * NL + t0 + tb) * NC + h * 64;
#pragma unroll
    for (int j = 0; j < 8; j++) {
        *reinterpret_cast<uint32_t*>(ab + (size_t)g * NC + j * 8 + tq * 2) =
            packbf(O[j][0] * i0, O[j][1] * i0);
        *reinterpret_cast<uint32_t*>(ab + (size_t)(g + 8) * NC + j * 8 + tq * 2) =
            packbf(O[j][2] * i1, O[j][3] * i1);
    }
}

// ===========================================================================
extern "C" void kernel_launch(void* const* d_in, const int* in_sizes, int n_in,
                              void* d_out, int out_size)
{
    const float* x      = (const float*)d_in[0];
    const float* ctx    = (const float*)d_in[1];
    const float* norm_w = (const float*)d_in[2];
    const float* norm_b = (const float*)d_in[3];
    const float* q_w    = (const float*)d_in[4];
    const float* q_b    = (const float*)d_in[5];
    const float* kv_w   = (const float*)d_in[6];
    const float* kv_b   = (const float*)d_in[7];
    const float* proj_w = (const float*)d_in[8];
    const float* proj_b = (const float*)d_in[9];
    float* out = (float*)d_out;

    __nv_bfloat16 *xnT, *cn, *qp, *kvp, *aT, *qwb, *kvwb, *pwb;
    cudaGetSymbolAddress((void**)&xnT,  g_xnT);
    cudaGetSymbolAddress((void**)&cn,   g_cn);
    cudaGetSymbolAddress((void**)&qp,   g_q);
    cudaGetSymbolAddress((void**)&kvp,  g_kv);
    cudaGetSymbolAddress((void**)&aT,   g_aT);
    cudaGetSymbolAddress((void**)&qwb,  g_qw);
    cudaGetSymbolAddress((void**)&kvwb, g_kvw);
    cudaGetSymbolAddress((void**)&pwb,  g_pw);

    cudaFuncSetAttribute(attn_bf16,
                         cudaFuncAttributeMaxDynamicSharedMemorySize, ATTN_SMEM);
    cudaFuncSetAttribute(gemm_bf16<0>,
                         cudaFuncAttributeMaxDynamicSharedMemorySize, GEMM_SMEM);
    cudaFuncSetAttribute(gemm_bf16<1>,
                         cudaFuncAttributeMaxDynamicSharedMemorySize, GEMM_SMEM);
    cudaFuncSetAttribute(gemm_bf16<2>,
                         cudaFuncAttributeMaxDynamicSharedMemorySize, GEMM_SMEM);

    // Weights -> bf16
    cvt_bf16_kernel<<<256, 256>>>(q_w,    qwb,  NC * NC / 4);
    cvt_bf16_kernel<<<512, 256>>>(kv_w,   kvwb, 2 * NC * NC / 4);
    cvt_bf16_kernel<<<256, 256>>>(proj_w, pwb,  NC * NC / 4);

    // GroupNorm: x -> xnT bf16 [l][c]; ctx -> cn bf16 [c][l]
    groupnorm_kernel<true ><<<NB * NG, 256>>>(x,   norm_w, norm_b, xnT);
    groupnorm_kernel<false><<<NB * NG, 256>>>(ctx, norm_w, norm_b, cn);

    // qT[b,l,o] = (xnT(l,c) . q_w(o,c)^T + q_b[o]) * 0.125   -> bf16
    gemm_bf16<2><<<dim3(4, 4, NB), 256, GEMM_SMEM>>>(
        xnT, (long long)NL * NC, qwb, 0, qp, (long long)NL * NC,
        q_b, nullptr, 0, NC, NC);

    // kv[b,c,o] = cn(c,l) . kv_w(o,l)^T + kv_b[o]            -> bf16
    gemm_bf16<1><<<dim3(8, 4, NB), 256, GEMM_SMEM>>>(
        cn, (long long)NC * NC, kvwb, 0, kvp, (long long)NC * 2 * NC,
        kv_b, nullptr, 0, 2 * NC, NC);

    // attention -> aT[b,l,c] bf16
    attn_bf16<<<dim3(4, NB * 8), 256, ATTN_SMEM>>>(qp, kvp, aT);

    // out[b,o,l] = x + proj_w(o,c) . aT(l,c)^T + proj_b[o]   (fp32)
    gemm_bf16<0><<<dim3(4, 4, NB), 256, GEMM_SMEM>>>(
        pwb, 0, aT, (long long)NL * NC, out, (long long)NC * NL,
        proj_b, x, (long long)NC * NL, NL, NC);
}